// round 12
// baseline (speedup 1.0000x reference)
#include <cuda_runtime.h>

typedef unsigned long long u64;

#define NELEC 16
#define NNUC  4
#define DDIM  128
#define KDIM  64
#define FDIM  32
#define HDIM  45
#define E0    112
#define E1    128
#define E2    64
#define ETOT  304
#define TPB   512
#define PAD   68
#define TGRID 4096
#define TMAX  20.0f

// per-elem strides
#define ELEC_S 2048
#define HX_S   1088
#define WEH_S  8704
#define Z_S    1088

// ---- shared memory layout (float offsets), 2 batch elems per CTA ----
#define OFF_ELEC 0           // 2*2048 = 4096
#define OFF_HX0  4096        // 2*1088 = 2176
#define OFF_HX1  6272        // 2*1088 = 2176
#define OFF_WEH  8448        // 2*8704 = 17408 (elem0 region doubles as hW0 stage)
#define OFF_Z    25856       // 2*1088 = 2176
#define OFF_GH0  28032       // 8192 (gW even-j buffer)
#define OFF_GH1  36224       // 8192 (gW odd-j / hW1 buffer)
#define OFF_NUC  44416       // 272
#define OFF_D    44688       // 2*304 = 608
#define OFF_SEND 45296       // 304 ints
#define OFF_RS   45600       // 96
#define OFF_CO   45696       // 12
#define OFF_DEG  45708       // 48 ints
#define OFF_EDG  45756       // 384 ints
#define SMEM_FLOATS 46140
#define SMEM_BYTES (SMEM_FLOATS * 4)    // 184560 B -> 1 CTA/SM

__device__ __forceinline__ u64 ffma2(u64 a, u64 b, u64 c) {
    u64 d; asm("fma.rn.f32x2 %0,%1,%2,%3;" : "=l"(d) : "l"(a), "l"(b), "l"(c)); return d;
}
__device__ __forceinline__ u64 pack2(float x, float y) {
    u64 r; asm("mov.b64 %0,{%1,%2};" : "=l"(r) : "f"(x), "f"(y)); return r;
}
__device__ __forceinline__ void unpack2(u64 v, float& x, float& y) {
    asm("mov.b64 {%0,%1},%2;" : "=f"(x), "=f"(y) : "l"(v));
}

// per-launch precomputed MLP table: we[lj][grid][k]  (9.4 MB, L2-resident)
__device__ float g_tab[9ULL * TGRID * KDIM];

// receiver CSR (LOCAL per-j edge indices), rebuilt every launch
__device__ int g_deg[3][NELEC];
__device__ int g_edge[3][NELEC][8];

__global__ void csr_kernel(const int* __restrict__ same_r,
                           const int* __restrict__ anti_r,
                           const int* __restrict__ ne_r) {
    if (blockIdx.x == 0 && threadIdx.x == 0) {
        for (int j = 0; j < 3; j++)
            for (int r = 0; r < NELEC; r++) g_deg[j][r] = 0;
        for (int e = 0; e < E0; e++) {
            int r = same_r[e]; int c = g_deg[0][r];
            if (c < 8) g_edge[0][r][c] = e;
            g_deg[0][r] = c + 1;
        }
        for (int e = 0; e < E1; e++) {
            int r = anti_r[e]; int c = g_deg[1][r];
            if (c < 8) g_edge[1][r][c] = e;
            g_deg[1][r] = c + 1;
        }
        for (int e = 0; e < E2; e++) {
            int r = ne_r[e]; int c = g_deg[2][r];
            if (c < 8) g_edge[2][r][c] = e;
            g_deg[2][r] = c + 1;
        }
    }
}

// ---- table precompute: we[k](d) on a uniform grid, per (l,j), packed fp32x2 ----
#define TK_SMEM_FLOATS 22064
__global__ __launch_bounds__(256, 1)
void table_kernel(const float* __restrict__ wW1,
                  const float* __restrict__ wb1,
                  const float* __restrict__ wW2) {
    extern __shared__ float ts[];
    float* sW1  = ts;            // [32][48] padded
    float* sb1  = ts + 1536;     // [48] padded
    float* sW2t = ts + 1584;     // [64][48] padded, transposed
    float* tile = ts + 4656;     // [256][68]
    int lj = blockIdx.x;
    int tid = threadIdx.x;

    for (int i = tid; i < FDIM * HDIM; i += 256) {
        int f = i / HDIM, h = i - f * HDIM;
        sW1[f * 48 + h] = wW1[lj * FDIM * HDIM + i];
    }
    if (tid < HDIM) sb1[tid] = wb1[lj * HDIM + tid];
    for (int i = tid; i < HDIM * KDIM; i += 256) {
        int k = i / HDIM, h = i - k * HDIM;
        sW2t[k * 48 + h] = wW2[lj * HDIM * KDIM + h * KDIM + k];
    }
    for (int i = tid; i < FDIM; i += 256) {
        sW1[i * 48 + 45] = 0.f; sW1[i * 48 + 46] = 0.f; sW1[i * 48 + 47] = 0.f;
    }
    for (int i = tid; i < KDIM; i += 256) {
        sW2t[i * 48 + 45] = 0.f; sW2t[i * 48 + 46] = 0.f; sW2t[i * 48 + 47] = 0.f;
    }
    if (tid < 3) sb1[45 + tid] = 0.f;
    __syncthreads();

    int p = blockIdx.y * 256 + tid;
    float d = p * (TMAX / (float)(TGRID - 1));
    float env = d * d * __expf(-d);

    u64 hid2[24];
    {
        const ulonglong2* bv = (const ulonglong2*)sb1;
#pragma unroll
        for (int i = 0; i < 12; i++) {
            ulonglong2 bb = bv[i];
            hid2[2 * i] = bb.x; hid2[2 * i + 1] = bb.y;
        }
    }
#pragma unroll 4
    for (int f = 0; f < FDIM; f++) {
        float q = f * (1.0f / 31.0f);
        float mu = 10.0f * q * q;
        float sg = (1.0f + 10.0f * q) * (1.0f / 7.0f);
        float t = d - mu;
        float fe = env * __expf(-t * t / (sg * sg));
        u64 fe2 = pack2(fe, fe);
        const ulonglong2* w1f = (const ulonglong2*)(sW1 + f * 48);
#pragma unroll
        for (int h = 0; h < 12; h++) {
            ulonglong2 w = w1f[h];
            hid2[2 * h]     = ffma2(fe2, w.x, hid2[2 * h]);
            hid2[2 * h + 1] = ffma2(fe2, w.y, hid2[2 * h + 1]);
        }
    }
#pragma unroll
    for (int i = 0; i < 24; i++) {
        float x, y; unpack2(hid2[i], x, y);
        x = __fdividef(x, 1.0f + __expf(-x));
        y = __fdividef(y, 1.0f + __expf(-y));
        hid2[i] = pack2(x, y);
    }

    for (int kk = 0; kk < KDIM; kk += 4) {
        const ulonglong2* r0 = (const ulonglong2*)(sW2t + (kk + 0) * 48);
        const ulonglong2* r1 = (const ulonglong2*)(sW2t + (kk + 1) * 48);
        const ulonglong2* r2 = (const ulonglong2*)(sW2t + (kk + 2) * 48);
        const ulonglong2* r3 = (const ulonglong2*)(sW2t + (kk + 3) * 48);
        u64 p0 = 0, p1 = 0, p2 = 0, p3 = 0;
        u64 q0 = 0, q1 = 0, q2 = 0, q3 = 0;
#pragma unroll
        for (int h = 0; h < 12; h++) {
            u64 h0 = hid2[2 * h], h1 = hid2[2 * h + 1];
            ulonglong2 w0 = r0[h], w1 = r1[h], w2 = r2[h], w3 = r3[h];
            p0 = ffma2(h0, w0.x, p0); q0 = ffma2(h1, w0.y, q0);
            p1 = ffma2(h0, w1.x, p1); q1 = ffma2(h1, w1.y, q1);
            p2 = ffma2(h0, w2.x, p2); q2 = ffma2(h1, w2.y, q2);
            p3 = ffma2(h0, w3.x, p3); q3 = ffma2(h1, w3.y, q3);
        }
        float4 res;
        float ax_, bx_, cx_, dx_;
        unpack2(p0, ax_, bx_); unpack2(q0, cx_, dx_);
        res.x = (ax_ + bx_) + (cx_ + dx_);
        unpack2(p1, ax_, bx_); unpack2(q1, cx_, dx_);
        res.y = (ax_ + bx_) + (cx_ + dx_);
        unpack2(p2, ax_, bx_); unpack2(q2, cx_, dx_);
        res.z = (ax_ + bx_) + (cx_ + dx_);
        unpack2(p3, ax_, bx_); unpack2(q3, cx_, dx_);
        res.w = (ax_ + bx_) + (cx_ + dx_);
        *(float4*)(tile + tid * PAD + kk) = res;
    }
    __syncthreads();
    float4* dst = (float4*)(g_tab + ((size_t)lj * TGRID + blockIdx.y * 256) * KDIM);
    for (int i = tid; i < 256 * 16; i += 256) {
        int pl = i >> 4, k4 = i & 15;
        dst[pl * 16 + k4] = *(const float4*)(tile + pl * PAD + k4 * 4);
    }
}

__global__ __launch_bounds__(TPB, 1)
void schnet_kernel(const float* __restrict__ rs, const float* __restrict__ coords,
                   const float* __restrict__ Xtab, const float* __restrict__ Yw,
                   const float* __restrict__ h0tab, const float* __restrict__ hW,
                   const float* __restrict__ gW,
                   const int* __restrict__ same_s, const int* __restrict__ same_r,
                   const int* __restrict__ anti_s, const int* __restrict__ anti_r,
                   const int* __restrict__ ne_s, const int* __restrict__ ne_r,
                   float* __restrict__ out) {
    extern __shared__ float sm[];
    const int tid = threadIdx.x;
    const int b0 = blockIdx.x * 2;   // two batch elems per CTA

    float* s_elec = sm + OFF_ELEC;
    float* s_hx0  = sm + OFF_HX0;
    float* s_hx1  = sm + OFF_HX1;
    float* s_weh  = sm + OFF_WEH;
    float* s_z    = sm + OFF_Z;
    float* s_gh0  = sm + OFF_GH0;
    float* s_gh1  = sm + OFF_GH1;
    float* s_nuc  = sm + OFF_NUC;
    float* s_d    = sm + OFF_D;
    int*   s_send = (int*)(sm + OFF_SEND);
    float* s_rs   = sm + OFF_RS;
    float* s_co   = sm + OFF_CO;
    int*   s_deg  = (int*)(sm + OFF_DEG);
    int*   s_edg  = (int*)(sm + OFF_EDG);

    // ---- block init ----
    for (int i = tid; i < 2 * NELEC * 3; i += TPB) s_rs[i] = rs[b0 * NELEC * 3 + i];
    for (int i = tid; i < NNUC * 3; i += TPB) s_co[i] = coords[i];
    for (int i = tid; i < 2 * NELEC * DDIM; i += TPB) s_elec[i] = Xtab[i & (DDIM - 1)];
    for (int i = tid; i < NNUC * KDIM; i += TPB)
        s_nuc[(i >> 6) * PAD + (i & 63)] = Yw[i];
    for (int i = tid; i < E0; i += TPB) s_send[i] = same_s[i];
    for (int i = tid; i < E1; i += TPB) s_send[E0 + i] = anti_s[i];
    for (int i = tid; i < E2; i += TPB) s_send[E0 + E1 + i] = ne_s[i];
    for (int i = tid; i < 3 * NELEC; i += TPB) s_deg[i] = ((const int*)g_deg)[i];
    for (int i = tid; i < 3 * NELEC * 8; i += TPB) s_edg[i] = ((const int*)g_edge)[i];
    __syncthreads();

    // ---- edge distances (both elems) ----
    for (int ee = tid; ee < 2 * ETOT; ee += TPB) {
        int eb = (ee < ETOT) ? 0 : 1;
        int e = ee - eb * ETOT;
        const float* rsE = s_rs + eb * 48;
        int s = s_send[e];
        float ax, ay, az, bx, by, bz;
        if (e < E0 + E1) {
            int r = (e < E0) ? same_r[e] : anti_r[e - E0];
            ax = rsE[s * 3 + 0]; ay = rsE[s * 3 + 1]; az = rsE[s * 3 + 2];
            bx = rsE[r * 3 + 0]; by = rsE[r * 3 + 1]; bz = rsE[r * 3 + 2];
        } else {
            int r = ne_r[e - E0 - E1];
            ax = s_co[s * 3 + 0]; ay = s_co[s * 3 + 1]; az = s_co[s * 3 + 2];
            bx = rsE[r * 3 + 0]; by = rsE[r * 3 + 1]; bz = rsE[r * 3 + 2];
        }
        float dx = ax - bx, dy = ay - by, dz = az - bz;
        s_d[ee] = sqrtf(dx * dx + dy * dy + dz * dz);
    }
    __syncthreads();

    const int wid  = tid >> 5;
    const int c2   = tid & 31;
    const int web  = wid >> 3;            // warp's batch elem
    const int sw   = wid & 7;             // role within elem
    const int rowb = (sw & 3) * 4;        // 4-row block
    const int half = (sw >> 2) * 64;      // column half
    float* elecE = s_elec + web * ELEC_S;
    float* zE    = s_z + web * Z_S;

    // ================= layer loop =================
    for (int l = 0; l < 3; l++) {
        // ---- hx phase (both j=0,1, both elems) ----
        if (l == 0) {
            for (int i = tid; i < 2 * NELEC * KDIM; i += TPB) {
                int eb = i >> 10, r = (i >> 6) & 15, k = i & 63;
                s_hx0[eb * HX_S + r * PAD + k] = h0tab[k];
                s_hx1[eb * HX_S + r * PAD + k] = h0tab[KDIM + k];
            }
            __syncthreads();
        } else {
            // hW1 for this layer was pre-staged into gh1 during prev layer's j2.
            const float4* h0src = (const float4*)(hW + (size_t)((l - 1) * 2 + 0) * DDIM * KDIM);
            for (int i = tid; i < DDIM * KDIM / 4; i += TPB)
                ((float4*)s_weh)[i] = h0src[i];     // elem0 weh region = hW0 stage
            __syncthreads();
            {
                const float* hWs = (sw >> 2) ? s_gh1 : s_weh;
                float* dsthx     = ((sw >> 2) ? s_hx1 : s_hx0) + web * HX_S;
                u64 h0 = 0, h1 = 0, h2 = 0, h3 = 0;
                const float4* e0 = (const float4*)(elecE + (rowb + 0) * DDIM);
                const float4* e1 = (const float4*)(elecE + (rowb + 1) * DDIM);
                const float4* e2 = (const float4*)(elecE + (rowb + 2) * DDIM);
                const float4* e3 = (const float4*)(elecE + (rowb + 3) * DDIM);
                for (int d4 = 0; d4 < DDIM / 4; d4++) {
                    float4 va = e0[d4], vb = e1[d4], vc = e2[d4], vd = e3[d4];
                    u64 w0 = *(const u64*)(hWs + (d4 * 4 + 0) * KDIM + c2 * 2);
                    u64 w1 = *(const u64*)(hWs + (d4 * 4 + 1) * KDIM + c2 * 2);
                    u64 w2 = *(const u64*)(hWs + (d4 * 4 + 2) * KDIM + c2 * 2);
                    u64 w3 = *(const u64*)(hWs + (d4 * 4 + 3) * KDIM + c2 * 2);
                    h0 = ffma2(pack2(va.x, va.x), w0, h0);
                    h1 = ffma2(pack2(vb.x, vb.x), w0, h1);
                    h2 = ffma2(pack2(vc.x, vc.x), w0, h2);
                    h3 = ffma2(pack2(vd.x, vd.x), w0, h3);
                    h0 = ffma2(pack2(va.y, va.y), w1, h0);
                    h1 = ffma2(pack2(vb.y, vb.y), w1, h1);
                    h2 = ffma2(pack2(vc.y, vc.y), w1, h2);
                    h3 = ffma2(pack2(vd.y, vd.y), w1, h3);
                    h0 = ffma2(pack2(va.z, va.z), w2, h0);
                    h1 = ffma2(pack2(vb.z, vb.z), w2, h1);
                    h2 = ffma2(pack2(vc.z, vc.z), w2, h2);
                    h3 = ffma2(pack2(vd.z, vd.z), w2, h3);
                    h0 = ffma2(pack2(va.w, va.w), w3, h0);
                    h1 = ffma2(pack2(vb.w, vb.w), w3, h1);
                    h2 = ffma2(pack2(vc.w, vc.w), w3, h2);
                    h3 = ffma2(pack2(vd.w, vd.w), w3, h3);
                }
                *(u64*)(dsthx + (rowb + 0) * PAD + c2 * 2) = h0;
                *(u64*)(dsthx + (rowb + 1) * PAD + c2 * 2) = h1;
                *(u64*)(dsthx + (rowb + 2) * PAD + c2 * 2) = h2;
                *(u64*)(dsthx + (rowb + 3) * PAD + c2 * 2) = h3;
            }
            __syncthreads();
        }

        // persistent update accumulators across j
        u64 a0 = 0ULL, a1 = 0ULL, a2 = 0ULL, a3 = 0ULL;

        for (int j = 0; j < 3; j++) {
            int Ej, base;
            if (j == 0)      { Ej = E0; base = 0;       }
            else if (j == 1) { Ej = E1; base = E0;      }
            else             { Ej = E2; base = E0 + E1; }
            int nact = 4 * Ej;   // 2 lanes/edge * 2 elems * Ej = 448 / 512 / 256

            // ---- edge MLP: team of 2 lanes per edge, 32 k each ----
            if (tid < nact) {
                int t = tid >> 1, q = tid & 1;     // t: 0..2*Ej-1, q: k-half
                int eb, e;
                if (j == 0)      { eb = (t >= E0) ? 1 : 0; e = t - eb * E0; }
                else if (j == 1) { eb = t >> 7; e = t & 127; }
                else             { eb = t >> 6; e = t & 63; }
                float d = s_d[eb * ETOT + base + e];
                float f = fminf(d, TMAX) * ((float)(TGRID - 1) / TMAX);
                int ii = (int)f;
                if (ii > TGRID - 2) ii = TGRID - 2;
                float fr = f - (float)ii;
                const float4* trow = (const float4*)(g_tab + ((size_t)(l * 3 + j) * TGRID + ii) * KDIM) + q * 8;
                int snd = s_send[base + e];
                const float* hxb;
                if (j == 0)      hxb = s_hx0 + eb * HX_S;
                else if (j == 1) hxb = s_hx1 + eb * HX_S;
                else             hxb = s_nuc;
                const float* hx = hxb + snd * PAD + q * 32;
                float* o = s_weh + eb * WEH_S + e * PAD + q * 32;
#pragma unroll
                for (int m = 0; m < 8; m++) {
                    float4 ta = __ldg(trow + m);
                    float4 tb = __ldg(trow + 16 + m);
                    float4 h4 = *(const float4*)(hx + m * 4);
                    float4 r;
                    r.x = fmaf(fr, tb.x - ta.x, ta.x) * h4.x;
                    r.y = fmaf(fr, tb.y - ta.y, ta.y) * h4.y;
                    r.z = fmaf(fr, tb.z - ta.z, ta.z) * h4.z;
                    r.w = fmaf(fr, tb.w - ta.w, ta.w) * h4.w;
                    *(float4*)(o + m * 4) = r;
                }
            } else if (j == 0) {
                // 64 idle threads stage gW[l,0] -> gh0
                const float4* gsrc = (const float4*)(gW + (size_t)(l * 3 + 0) * KDIM * DDIM);
                for (int i = tid - nact; i < KDIM * DDIM / 4; i += TPB - nact)
                    ((float4*)s_gh0)[i] = gsrc[i];
            } else if (j == 2 && l < 2) {
                // 256 idle threads pre-stage next layer's hW1 -> gh1
                const float4* hsrc = (const float4*)(hW + (size_t)(l * 2 + 1) * DDIM * KDIM);
                for (int i = tid - nact; i < DDIM * KDIM / 4; i += TPB - nact)
                    ((float4*)s_gh1)[i] = hsrc[i];
            }
            __syncthreads();

            // ---- receiver gather into z (half-warp per row, both elems) ----
            {
                int t = tid & 255, eb = tid >> 8;
                int rr = t >> 4, cc = t & 15;
                const float* wehE = s_weh + eb * WEH_S;
                int dg = s_deg[j * NELEC + rr];
                const int* er = s_edg + (j * NELEC + rr) * 8;
                float4 acc = make_float4(0.f, 0.f, 0.f, 0.f);
                for (int i = 0; i < dg; i++) {
                    float4 v = *(const float4*)(wehE + er[i] * PAD + cc * 4);
                    acc.x += v.x; acc.y += v.y; acc.z += v.z; acc.w += v.w;
                }
                *(float4*)(s_z + eb * Z_S + rr * PAD + cc * 4) = acc;
            }
            __syncthreads();

            // ---- z @ gW : per warp 4 rows × 64-col half of its elem ----
            {
                const float* ghc = (j == 1) ? s_gh1 : s_gh0;
                const float4* z0 = (const float4*)(zE + (rowb + 0) * PAD);
                const float4* z1 = (const float4*)(zE + (rowb + 1) * PAD);
                const float4* z2 = (const float4*)(zE + (rowb + 2) * PAD);
                const float4* z3 = (const float4*)(zE + (rowb + 3) * PAD);
#pragma unroll 2
                for (int k4 = 0; k4 < 16; k4++) {
                    float4 za = z0[k4], zb = z1[k4], zc = z2[k4], zd = z3[k4];
                    u64 w;
                    w = *(const u64*)(ghc + (k4 * 4 + 0) * DDIM + half + c2 * 2);
                    a0 = ffma2(pack2(za.x, za.x), w, a0);
                    a1 = ffma2(pack2(zb.x, zb.x), w, a1);
                    a2 = ffma2(pack2(zc.x, zc.x), w, a2);
                    a3 = ffma2(pack2(zd.x, zd.x), w, a3);
                    w = *(const u64*)(ghc + (k4 * 4 + 1) * DDIM + half + c2 * 2);
                    a0 = ffma2(pack2(za.y, za.y), w, a0);
                    a1 = ffma2(pack2(zb.y, zb.y), w, a1);
                    a2 = ffma2(pack2(zc.y, zc.y), w, a2);
                    a3 = ffma2(pack2(zd.y, zd.y), w, a3);
                    w = *(const u64*)(ghc + (k4 * 4 + 2) * DDIM + half + c2 * 2);
                    a0 = ffma2(pack2(za.z, za.z), w, a0);
                    a1 = ffma2(pack2(zb.z, zb.z), w, a1);
                    a2 = ffma2(pack2(zc.z, zc.z), w, a2);
                    a3 = ffma2(pack2(zd.z, zd.z), w, a3);
                    w = *(const u64*)(ghc + (k4 * 4 + 3) * DDIM + half + c2 * 2);
                    a0 = ffma2(pack2(za.w, za.w), w, a0);
                    a1 = ffma2(pack2(zb.w, zb.w), w, a1);
                    a2 = ffma2(pack2(zc.w, zc.w), w, a2);
                    a3 = ffma2(pack2(zd.w, zd.w), w, a3);
                }
                // embedded staging of the NEXT j's gW (buffers are free now)
                if (j == 0) {
                    const float4* gsrc = (const float4*)(gW + (size_t)(l * 3 + 1) * KDIM * DDIM);
                    for (int i = tid; i < KDIM * DDIM / 4; i += TPB)
                        ((float4*)s_gh1)[i] = gsrc[i];
                } else if (j == 1) {
                    const float4* gsrc = (const float4*)(gW + (size_t)(l * 3 + 2) * KDIM * DDIM);
                    for (int i = tid; i < KDIM * DDIM / 4; i += TPB)
                        ((float4*)s_gh0)[i] = gsrc[i];
                }
            }
            __syncthreads();
        }

        // ---- fold register update into elec ----
        {
            float x, y;
            float* dst;
            dst = elecE + (rowb + 0) * DDIM + half + c2 * 2;
            unpack2(a0, x, y); dst[0] += x; dst[1] += y;
            dst = elecE + (rowb + 1) * DDIM + half + c2 * 2;
            unpack2(a1, x, y); dst[0] += x; dst[1] += y;
            dst = elecE + (rowb + 2) * DDIM + half + c2 * 2;
            unpack2(a2, x, y); dst[0] += x; dst[1] += y;
            dst = elecE + (rowb + 3) * DDIM + half + c2 * 2;
            unpack2(a3, x, y); dst[0] += x; dst[1] += y;
        }
        __syncthreads();
    }

    // ---- write result (both elems contiguous) ----
    for (int i = tid; i < 2 * NELEC * DDIM / 4; i += TPB)
        ((float4*)(out + b0 * NELEC * DDIM))[i] = ((const float4*)s_elec)[i];
}

extern "C" void kernel_launch(void* const* d_in, const int* in_sizes, int n_in,
                              void* d_out, int out_size) {
    const float* rs     = (const float*)d_in[0];
    const float* coords = (const float*)d_in[1];
    const float* Xtab   = (const float*)d_in[2];
    const float* Yw     = (const float*)d_in[3];
    const float* wW1    = (const float*)d_in[4];
    const float* wb1    = (const float*)d_in[5];
    const float* wW2    = (const float*)d_in[6];
    const float* h0tab  = (const float*)d_in[7];
    const float* hW     = (const float*)d_in[8];
    const float* gW     = (const float*)d_in[9];
    const int* same_s   = (const int*)d_in[10];
    const int* same_r   = (const int*)d_in[11];
    const int* anti_s   = (const int*)d_in[12];
    const int* anti_r   = (const int*)d_in[13];
    const int* ne_s     = (const int*)d_in[14];
    const int* ne_r     = (const int*)d_in[15];
    float* out = (float*)d_out;

    int B = in_sizes[0] / (NELEC * 3);

    cudaFuncSetAttribute(table_kernel,
                         cudaFuncAttributeMaxDynamicSharedMemorySize, TK_SMEM_FLOATS * 4);
    cudaFuncSetAttribute(schnet_kernel,
                         cudaFuncAttributeMaxDynamicSharedMemorySize, SMEM_BYTES);

    table_kernel<<<dim3(9, TGRID / 256), 256, TK_SMEM_FLOATS * 4>>>(wW1, wb1, wW2);
    csr_kernel<<<1, 32>>>(same_r, anti_r, ne_r);
    schnet_kernel<<<B / 2, TPB, SMEM_BYTES>>>(rs, coords, Xtab, Yw, h0tab, hW, gW,
                                              same_s, same_r, anti_s, anti_r,
                                              ne_s, ne_r, out);
}

// round 13
// speedup vs baseline: 1.2662x; 1.2662x over previous
#include <cuda_runtime.h>

typedef unsigned long long u64;

#define NELEC 16
#define NNUC  4
#define DDIM  128
#define KDIM  64
#define FDIM  32
#define HDIM  45
#define E0    112
#define E1    128
#define E2    64
#define ETOT  304
#define TPB   512
#define PAD   68
#define TGRID 2048
#define TMAX  20.0f

// per-elem strides
#define ELEC_S 2048
#define HX_S   1088
#define WEH_S  8704
#define Z_S    1088

// ---- shared memory layout (float offsets), 2 batch elems per CTA ----
#define OFF_ELEC 0           // 2*2048 = 4096
#define OFF_HX0  4096        // 2*1088 = 2176
#define OFF_HX1  6272        // 2*1088 = 2176
#define OFF_WEH  8448        // 2*8704 = 17408 (elem0 region doubles as hW0 stage)
#define OFF_Z    25856       // 2*1088 = 2176
#define OFF_GH   28032       // 8192 (gW / hW1 stage buffer)
#define OFF_NUC  36224       // 272
#define OFF_D    36496       // 2*304 = 608
#define OFF_SEND 37104       // 304 ints
#define OFF_RS   37408       // 96
#define OFF_CO   37504       // 12
#define OFF_DEG  37516       // 48 ints
#define OFF_EDG  37564       // 384 ints
#define SMEM_FLOATS 37948
#define SMEM_BYTES (SMEM_FLOATS * 4)    // 151792 B -> 1 CTA/SM

__device__ __forceinline__ u64 ffma2(u64 a, u64 b, u64 c) {
    u64 d; asm("fma.rn.f32x2 %0,%1,%2,%3;" : "=l"(d) : "l"(a), "l"(b), "l"(c)); return d;
}
__device__ __forceinline__ u64 pack2(float x, float y) {
    u64 r; asm("mov.b64 %0,{%1,%2};" : "=l"(r) : "f"(x), "f"(y)); return r;
}
__device__ __forceinline__ void unpack2(u64 v, float& x, float& y) {
    asm("mov.b64 {%0,%1},%2;" : "=f"(x), "=f"(y) : "l"(v));
}

// per-launch precomputed MLP table: we[lj][grid][k]  (4.7 MB, L2-resident)
__device__ float g_tab[9ULL * TGRID * KDIM];

// receiver CSR (LOCAL per-j edge indices), rebuilt every launch
__device__ int g_deg[3][NELEC];
__device__ int g_edge[3][NELEC][8];

__global__ void csr_kernel(const int* __restrict__ same_r,
                           const int* __restrict__ anti_r,
                           const int* __restrict__ ne_r) {
    if (blockIdx.x == 0 && threadIdx.x == 0) {
        for (int j = 0; j < 3; j++)
            for (int r = 0; r < NELEC; r++) g_deg[j][r] = 0;
        for (int e = 0; e < E0; e++) {
            int r = same_r[e]; int c = g_deg[0][r];
            if (c < 8) g_edge[0][r][c] = e;
            g_deg[0][r] = c + 1;
        }
        for (int e = 0; e < E1; e++) {
            int r = anti_r[e]; int c = g_deg[1][r];
            if (c < 8) g_edge[1][r][c] = e;
            g_deg[1][r] = c + 1;
        }
        for (int e = 0; e < E2; e++) {
            int r = ne_r[e]; int c = g_deg[2][r];
            if (c < 8) g_edge[2][r][c] = e;
            g_deg[2][r] = c + 1;
        }
    }
}

// ---- table precompute: we[k](d) on a uniform grid, per (l,j), packed fp32x2 ----
#define TK_SMEM_FLOATS 22064
__global__ __launch_bounds__(256, 1)
void table_kernel(const float* __restrict__ wW1,
                  const float* __restrict__ wb1,
                  const float* __restrict__ wW2) {
    extern __shared__ float ts[];
    float* sW1  = ts;            // [32][48] padded
    float* sb1  = ts + 1536;     // [48] padded
    float* sW2t = ts + 1584;     // [64][48] padded, transposed
    float* tile = ts + 4656;     // [256][68]
    int lj = blockIdx.x;
    int tid = threadIdx.x;

    for (int i = tid; i < FDIM * HDIM; i += 256) {
        int f = i / HDIM, h = i - f * HDIM;
        sW1[f * 48 + h] = wW1[lj * FDIM * HDIM + i];
    }
    if (tid < HDIM) sb1[tid] = wb1[lj * HDIM + tid];
    for (int i = tid; i < HDIM * KDIM; i += 256) {
        int k = i / HDIM, h = i - k * HDIM;
        sW2t[k * 48 + h] = wW2[lj * HDIM * KDIM + h * KDIM + k];
    }
    for (int i = tid; i < FDIM; i += 256) {
        sW1[i * 48 + 45] = 0.f; sW1[i * 48 + 46] = 0.f; sW1[i * 48 + 47] = 0.f;
    }
    for (int i = tid; i < KDIM; i += 256) {
        sW2t[i * 48 + 45] = 0.f; sW2t[i * 48 + 46] = 0.f; sW2t[i * 48 + 47] = 0.f;
    }
    if (tid < 3) sb1[45 + tid] = 0.f;
    __syncthreads();

    int p = blockIdx.y * 256 + tid;
    float d = p * (TMAX / (float)(TGRID - 1));
    float env = d * d * __expf(-d);

    u64 hid2[24];
    {
        const ulonglong2* bv = (const ulonglong2*)sb1;
#pragma unroll
        for (int i = 0; i < 12; i++) {
            ulonglong2 bb = bv[i];
            hid2[2 * i] = bb.x; hid2[2 * i + 1] = bb.y;
        }
    }
#pragma unroll 4
    for (int f = 0; f < FDIM; f++) {
        float q = f * (1.0f / 31.0f);
        float mu = 10.0f * q * q;
        float sg = (1.0f + 10.0f * q) * (1.0f / 7.0f);
        float t = d - mu;
        float fe = env * __expf(-t * t / (sg * sg));
        u64 fe2 = pack2(fe, fe);
        const ulonglong2* w1f = (const ulonglong2*)(sW1 + f * 48);
#pragma unroll
        for (int h = 0; h < 12; h++) {
            ulonglong2 w = w1f[h];
            hid2[2 * h]     = ffma2(fe2, w.x, hid2[2 * h]);
            hid2[2 * h + 1] = ffma2(fe2, w.y, hid2[2 * h + 1]);
        }
    }
#pragma unroll
    for (int i = 0; i < 24; i++) {
        float x, y; unpack2(hid2[i], x, y);
        x = __fdividef(x, 1.0f + __expf(-x));
        y = __fdividef(y, 1.0f + __expf(-y));
        hid2[i] = pack2(x, y);
    }

    for (int kk = 0; kk < KDIM; kk += 4) {
        const ulonglong2* r0 = (const ulonglong2*)(sW2t + (kk + 0) * 48);
        const ulonglong2* r1 = (const ulonglong2*)(sW2t + (kk + 1) * 48);
        const ulonglong2* r2 = (const ulonglong2*)(sW2t + (kk + 2) * 48);
        const ulonglong2* r3 = (const ulonglong2*)(sW2t + (kk + 3) * 48);
        u64 p0 = 0, p1 = 0, p2 = 0, p3 = 0;
        u64 q0 = 0, q1 = 0, q2 = 0, q3 = 0;
#pragma unroll
        for (int h = 0; h < 12; h++) {
            u64 h0 = hid2[2 * h], h1 = hid2[2 * h + 1];
            ulonglong2 w0 = r0[h], w1 = r1[h], w2 = r2[h], w3 = r3[h];
            p0 = ffma2(h0, w0.x, p0); q0 = ffma2(h1, w0.y, q0);
            p1 = ffma2(h0, w1.x, p1); q1 = ffma2(h1, w1.y, q1);
            p2 = ffma2(h0, w2.x, p2); q2 = ffma2(h1, w2.y, q2);
            p3 = ffma2(h0, w3.x, p3); q3 = ffma2(h1, w3.y, q3);
        }
        float4 res;
        float ax_, bx_, cx_, dx_;
        unpack2(p0, ax_, bx_); unpack2(q0, cx_, dx_);
        res.x = (ax_ + bx_) + (cx_ + dx_);
        unpack2(p1, ax_, bx_); unpack2(q1, cx_, dx_);
        res.y = (ax_ + bx_) + (cx_ + dx_);
        unpack2(p2, ax_, bx_); unpack2(q2, cx_, dx_);
        res.z = (ax_ + bx_) + (cx_ + dx_);
        unpack2(p3, ax_, bx_); unpack2(q3, cx_, dx_);
        res.w = (ax_ + bx_) + (cx_ + dx_);
        *(float4*)(tile + tid * PAD + kk) = res;
    }
    __syncthreads();
    float4* dst = (float4*)(g_tab + ((size_t)lj * TGRID + blockIdx.y * 256) * KDIM);
    for (int i = tid; i < 256 * 16; i += 256) {
        int pl = i >> 4, k4 = i & 15;
        dst[pl * 16 + k4] = *(const float4*)(tile + pl * PAD + k4 * 4);
    }
}

__global__ __launch_bounds__(TPB, 1)
void schnet_kernel(const float* __restrict__ rs, const float* __restrict__ coords,
                   const float* __restrict__ Xtab, const float* __restrict__ Yw,
                   const float* __restrict__ h0tab, const float* __restrict__ hW,
                   const float* __restrict__ gW,
                   const int* __restrict__ same_s, const int* __restrict__ same_r,
                   const int* __restrict__ anti_s, const int* __restrict__ anti_r,
                   const int* __restrict__ ne_s, const int* __restrict__ ne_r,
                   float* __restrict__ out) {
    extern __shared__ float sm[];
    const int tid = threadIdx.x;
    const int b0 = blockIdx.x * 2;   // two batch elems per CTA

    float* s_elec = sm + OFF_ELEC;
    float* s_hx0  = sm + OFF_HX0;
    float* s_hx1  = sm + OFF_HX1;
    float* s_weh  = sm + OFF_WEH;
    float* s_z    = sm + OFF_Z;
    float* s_gh   = sm + OFF_GH;
    float* s_nuc  = sm + OFF_NUC;
    float* s_d    = sm + OFF_D;
    int*   s_send = (int*)(sm + OFF_SEND);
    float* s_rs   = sm + OFF_RS;
    float* s_co   = sm + OFF_CO;
    int*   s_deg  = (int*)(sm + OFF_DEG);
    int*   s_edg  = (int*)(sm + OFF_EDG);

    // ---- block init ----
    for (int i = tid; i < 2 * NELEC * 3; i += TPB) s_rs[i] = rs[b0 * NELEC * 3 + i];
    for (int i = tid; i < NNUC * 3; i += TPB) s_co[i] = coords[i];
    for (int i = tid; i < 2 * NELEC * DDIM; i += TPB) s_elec[i] = Xtab[i & (DDIM - 1)];
    for (int i = tid; i < NNUC * KDIM; i += TPB)
        s_nuc[(i >> 6) * PAD + (i & 63)] = Yw[i];
    for (int i = tid; i < E0; i += TPB) s_send[i] = same_s[i];
    for (int i = tid; i < E1; i += TPB) s_send[E0 + i] = anti_s[i];
    for (int i = tid; i < E2; i += TPB) s_send[E0 + E1 + i] = ne_s[i];
    for (int i = tid; i < 3 * NELEC; i += TPB) s_deg[i] = ((const int*)g_deg)[i];
    for (int i = tid; i < 3 * NELEC * 8; i += TPB) s_edg[i] = ((const int*)g_edge)[i];
    __syncthreads();

    // ---- edge distances (both elems) ----
    for (int ee = tid; ee < 2 * ETOT; ee += TPB) {
        int eb = (ee < ETOT) ? 0 : 1;
        int e = ee - eb * ETOT;
        const float* rsE = s_rs + eb * 48;
        int s = s_send[e];
        float ax, ay, az, bx, by, bz;
        if (e < E0 + E1) {
            int r = (e < E0) ? same_r[e] : anti_r[e - E0];
            ax = rsE[s * 3 + 0]; ay = rsE[s * 3 + 1]; az = rsE[s * 3 + 2];
            bx = rsE[r * 3 + 0]; by = rsE[r * 3 + 1]; bz = rsE[r * 3 + 2];
        } else {
            int r = ne_r[e - E0 - E1];
            ax = s_co[s * 3 + 0]; ay = s_co[s * 3 + 1]; az = s_co[s * 3 + 2];
            bx = rsE[r * 3 + 0]; by = rsE[r * 3 + 1]; bz = rsE[r * 3 + 2];
        }
        float dx = ax - bx, dy = ay - by, dz = az - bz;
        s_d[ee] = sqrtf(dx * dx + dy * dy + dz * dz);
    }
    __syncthreads();

    const int wid  = tid >> 5;
    const int c2   = tid & 31;
    const int web  = wid >> 3;            // warp's batch elem
    const int sw   = wid & 7;             // role within elem
    const int rowb = (sw & 3) * 4;        // 4-row block
    const int half = (sw >> 2) * 64;      // column half
    float* elecE = s_elec + web * ELEC_S;
    float* zE    = s_z + web * Z_S;

    // ================= layer loop =================
    for (int l = 0; l < 3; l++) {
        // ---- hx phase (both j=0,1, both elems) ----
        if (l == 0) {
            for (int i = tid; i < 2 * NELEC * KDIM; i += TPB) {
                int eb = i >> 10, r = (i >> 6) & 15, k = i & 63;
                s_hx0[eb * HX_S + r * PAD + k] = h0tab[k];
                s_hx1[eb * HX_S + r * PAD + k] = h0tab[KDIM + k];
            }
            __syncthreads();
        } else {
            const float4* h0src = (const float4*)(hW + (size_t)((l - 1) * 2 + 0) * DDIM * KDIM);
            const float4* h1src = (const float4*)(hW + (size_t)((l - 1) * 2 + 1) * DDIM * KDIM);
            for (int i = tid; i < DDIM * KDIM / 4; i += TPB) {
                ((float4*)s_weh)[i] = h0src[i];     // elem0 weh region = hW0 stage
                ((float4*)s_gh)[i]  = h1src[i];     // gh = hW1 stage
            }
            __syncthreads();
            {
                const float* hWs = (sw >> 2) ? s_gh : s_weh;
                float* dsthx     = ((sw >> 2) ? s_hx1 : s_hx0) + web * HX_S;
                u64 h0 = 0, h1 = 0, h2 = 0, h3 = 0;
                const float4* e0 = (const float4*)(elecE + (rowb + 0) * DDIM);
                const float4* e1 = (const float4*)(elecE + (rowb + 1) * DDIM);
                const float4* e2 = (const float4*)(elecE + (rowb + 2) * DDIM);
                const float4* e3 = (const float4*)(elecE + (rowb + 3) * DDIM);
                for (int d4 = 0; d4 < DDIM / 4; d4++) {
                    float4 va = e0[d4], vb = e1[d4], vc = e2[d4], vd = e3[d4];
                    u64 w0 = *(const u64*)(hWs + (d4 * 4 + 0) * KDIM + c2 * 2);
                    u64 w1 = *(const u64*)(hWs + (d4 * 4 + 1) * KDIM + c2 * 2);
                    u64 w2 = *(const u64*)(hWs + (d4 * 4 + 2) * KDIM + c2 * 2);
                    u64 w3 = *(const u64*)(hWs + (d4 * 4 + 3) * KDIM + c2 * 2);
                    h0 = ffma2(pack2(va.x, va.x), w0, h0);
                    h1 = ffma2(pack2(vb.x, vb.x), w0, h1);
                    h2 = ffma2(pack2(vc.x, vc.x), w0, h2);
                    h3 = ffma2(pack2(vd.x, vd.x), w0, h3);
                    h0 = ffma2(pack2(va.y, va.y), w1, h0);
                    h1 = ffma2(pack2(vb.y, vb.y), w1, h1);
                    h2 = ffma2(pack2(vc.y, vc.y), w1, h2);
                    h3 = ffma2(pack2(vd.y, vd.y), w1, h3);
                    h0 = ffma2(pack2(va.z, va.z), w2, h0);
                    h1 = ffma2(pack2(vb.z, vb.z), w2, h1);
                    h2 = ffma2(pack2(vc.z, vc.z), w2, h2);
                    h3 = ffma2(pack2(vd.z, vd.z), w2, h3);
                    h0 = ffma2(pack2(va.w, va.w), w3, h0);
                    h1 = ffma2(pack2(vb.w, vb.w), w3, h1);
                    h2 = ffma2(pack2(vc.w, vc.w), w3, h2);
                    h3 = ffma2(pack2(vd.w, vd.w), w3, h3);
                }
                *(u64*)(dsthx + (rowb + 0) * PAD + c2 * 2) = h0;
                *(u64*)(dsthx + (rowb + 1) * PAD + c2 * 2) = h1;
                *(u64*)(dsthx + (rowb + 2) * PAD + c2 * 2) = h2;
                *(u64*)(dsthx + (rowb + 3) * PAD + c2 * 2) = h3;
            }
            __syncthreads();
        }

        // persistent update accumulators across j
        u64 a0 = 0ULL, a1 = 0ULL, a2 = 0ULL, a3 = 0ULL;

        for (int j = 0; j < 3; j++) {
            int Ej, base;
            if (j == 0)      { Ej = E0; base = 0;       }
            else if (j == 1) { Ej = E1; base = E0;      }
            else             { Ej = E2; base = E0 + E1; }
            int nact = 2 * Ej;

            // ---- edge MLP (table lerp, both elems) || gW staging by idle threads ----
            if (tid < nact) {
                int eb, e;
                if (j == 0)      { eb = tid / E0; e = tid - eb * E0; }
                else if (j == 1) { eb = tid >> 7; e = tid & 127; }
                else             { eb = tid >> 6; e = tid & 63; }
                float d = s_d[eb * ETOT + base + e];
                float f = fminf(d, TMAX) * ((float)(TGRID - 1) / TMAX);
                int ii = (int)f;
                if (ii > TGRID - 2) ii = TGRID - 2;
                float fr = f - (float)ii;
                const float4* t0 = (const float4*)(g_tab + ((size_t)(l * 3 + j) * TGRID + ii) * KDIM);
                int snd = s_send[base + e];
                const float* hxb;
                if (j == 0)      hxb = s_hx0 + eb * HX_S;
                else if (j == 1) hxb = s_hx1 + eb * HX_S;
                else             hxb = s_nuc;
                const float* hx = hxb + snd * PAD;
                float* o = s_weh + eb * WEH_S + e * PAD;
#pragma unroll
                for (int k4 = 0; k4 < 16; k4++) {
                    float4 ta = __ldg(t0 + k4);
                    float4 tb = __ldg(t0 + 16 + k4);
                    float4 h4 = *(const float4*)(hx + k4 * 4);
                    float4 r;
                    r.x = fmaf(fr, tb.x - ta.x, ta.x) * h4.x;
                    r.y = fmaf(fr, tb.y - ta.y, ta.y) * h4.y;
                    r.z = fmaf(fr, tb.z - ta.z, ta.z) * h4.z;
                    r.w = fmaf(fr, tb.w - ta.w, ta.w) * h4.w;
                    *(float4*)(o + k4 * 4) = r;
                }
            } else {
                const float4* gsrc = (const float4*)(gW + (size_t)(l * 3 + j) * KDIM * DDIM);
                for (int i = tid - nact; i < KDIM * DDIM / 4; i += TPB - nact)
                    ((float4*)s_gh)[i] = gsrc[i];
            }
            __syncthreads();

            // ---- receiver gather into z (half-warp per row, distinct, both elems) ----
            {
                int t = tid & 255, eb = tid >> 8;
                int rr = t >> 4, cc = t & 15;
                const float* wehE = s_weh + eb * WEH_S;
                int dg = s_deg[j * NELEC + rr];
                const int* er = s_edg + (j * NELEC + rr) * 8;
                float4 acc = make_float4(0.f, 0.f, 0.f, 0.f);
                for (int i = 0; i < dg; i++) {
                    float4 v = *(const float4*)(wehE + er[i] * PAD + cc * 4);
                    acc.x += v.x; acc.y += v.y; acc.z += v.z; acc.w += v.w;
                }
                *(float4*)(s_z + eb * Z_S + rr * PAD + cc * 4) = acc;
            }
            __syncthreads();

            // ---- z @ gW : per warp 4 rows × 64-col half of its elem ----
            {
                const float4* z0 = (const float4*)(zE + (rowb + 0) * PAD);
                const float4* z1 = (const float4*)(zE + (rowb + 1) * PAD);
                const float4* z2 = (const float4*)(zE + (rowb + 2) * PAD);
                const float4* z3 = (const float4*)(zE + (rowb + 3) * PAD);
#pragma unroll 2
                for (int k4 = 0; k4 < 16; k4++) {
                    float4 za = z0[k4], zb = z1[k4], zc = z2[k4], zd = z3[k4];
                    u64 w;
                    w = *(const u64*)(s_gh + (k4 * 4 + 0) * DDIM + half + c2 * 2);
                    a0 = ffma2(pack2(za.x, za.x), w, a0);
                    a1 = ffma2(pack2(zb.x, zb.x), w, a1);
                    a2 = ffma2(pack2(zc.x, zc.x), w, a2);
                    a3 = ffma2(pack2(zd.x, zd.x), w, a3);
                    w = *(const u64*)(s_gh + (k4 * 4 + 1) * DDIM + half + c2 * 2);
                    a0 = ffma2(pack2(za.y, za.y), w, a0);
                    a1 = ffma2(pack2(zb.y, zb.y), w, a1);
                    a2 = ffma2(pack2(zc.y, zc.y), w, a2);
                    a3 = ffma2(pack2(zd.y, zd.y), w, a3);
                    w = *(const u64*)(s_gh + (k4 * 4 + 2) * DDIM + half + c2 * 2);
                    a0 = ffma2(pack2(za.z, za.z), w, a0);
                    a1 = ffma2(pack2(zb.z, zb.z), w, a1);
                    a2 = ffma2(pack2(zc.z, zc.z), w, a2);
                    a3 = ffma2(pack2(zd.z, zd.z), w, a3);
                    w = *(const u64*)(s_gh + (k4 * 4 + 3) * DDIM + half + c2 * 2);
                    a0 = ffma2(pack2(za.w, za.w), w, a0);
                    a1 = ffma2(pack2(zb.w, zb.w), w, a1);
                    a2 = ffma2(pack2(zc.w, zc.w), w, a2);
                    a3 = ffma2(pack2(zd.w, zd.w), w, a3);
                }
            }
            __syncthreads();
        }

        // ---- fold register update into elec ----
        {
            float x, y;
            float* dst;
            dst = elecE + (rowb + 0) * DDIM + half + c2 * 2;
            unpack2(a0, x, y); dst[0] += x; dst[1] += y;
            dst = elecE + (rowb + 1) * DDIM + half + c2 * 2;
            unpack2(a1, x, y); dst[0] += x; dst[1] += y;
            dst = elecE + (rowb + 2) * DDIM + half + c2 * 2;
            unpack2(a2, x, y); dst[0] += x; dst[1] += y;
            dst = elecE + (rowb + 3) * DDIM + half + c2 * 2;
            unpack2(a3, x, y); dst[0] += x; dst[1] += y;
        }
        __syncthreads();
    }

    // ---- write result (both elems contiguous) ----
    for (int i = tid; i < 2 * NELEC * DDIM / 4; i += TPB)
        ((float4*)(out + b0 * NELEC * DDIM))[i] = ((const float4*)s_elec)[i];
}

extern "C" void kernel_launch(void* const* d_in, const int* in_sizes, int n_in,
                              void* d_out, int out_size) {
    const float* rs     = (const float*)d_in[0];
    const float* coords = (const float*)d_in[1];
    const float* Xtab   = (const float*)d_in[2];
    const float* Yw     = (const float*)d_in[3];
    const float* wW1    = (const float*)d_in[4];
    const float* wb1    = (const float*)d_in[5];
    const float* wW2    = (const float*)d_in[6];
    const float* h0tab  = (const float*)d_in[7];
    const float* hW     = (const float*)d_in[8];
    const float* gW     = (const float*)d_in[9];
    const int* same_s   = (const int*)d_in[10];
    const int* same_r   = (const int*)d_in[11];
    const int* anti_s   = (const int*)d_in[12];
    const int* anti_r   = (const int*)d_in[13];
    const int* ne_s     = (const int*)d_in[14];
    const int* ne_r     = (const int*)d_in[15];
    float* out = (float*)d_out;

    int B = in_sizes[0] / (NELEC * 3);

    cudaFuncSetAttribute(table_kernel,
                         cudaFuncAttributeMaxDynamicSharedMemorySize, TK_SMEM_FLOATS * 4);
    cudaFuncSetAttribute(schnet_kernel,
                         cudaFuncAttributeMaxDynamicSharedMemorySize, SMEM_BYTES);

    table_kernel<<<dim3(9, TGRID / 256), 256, TK_SMEM_FLOATS * 4>>>(wW1, wb1, wW2);
    csr_kernel<<<1, 32>>>(same_r, anti_r, ne_r);
    schnet_kernel<<<B / 2, TPB, SMEM_BYTES>>>(rs, coords, Xtab, Yw, h0tab, hW, gW,
                                              same_s, same_r, anti_s, anti_r,
                                              ne_s, ne_r, out);
}